// round 13
// baseline (speedup 1.0000x reference)
#include <cuda_runtime.h>
#include <math.h>

#define E 1024
#define H 4096

// Scratch (allocation-free per harness rules)
__device__ __align__(16) float g_xi[H];
__device__ __align__(16) float g_gates[4 * H];  // raw dot per stacked row
__device__ __align__(16) float g_h1[H];
__device__ int g_xi_done;     // blocks finished phase A   (target 512)
__device__ int g_gates_done;  // blocks finished phase B   (target 512)
__device__ int g_h1_done;     // blocks finished pointwise (target 512)
__device__ int g_hflag;

__device__ __forceinline__ float sigmoidf(float x) {
    return 1.0f / (1.0f + expf(-x));
}
__device__ __forceinline__ float dot4(float4 a, float4 b) {
    return a.x * b.x + a.y * b.y + a.z * b.z + a.w * b.w;
}

// ---------------------------------------------------------------------------
// K0: reset counters (graph replays reuse globals) + hflag = any(h0 != 0)
// ---------------------------------------------------------------------------
__global__ void k_init(const float* __restrict__ h0) {
    const int t = threadIdx.x;  // 256
    if (t == 0)  g_xi_done = 0;
    if (t == 32) g_gates_done = 0;
    if (t == 64) g_h1_done = 0;
    const float4* h4 = (const float4*)h0;
    int any = 0;
    #pragma unroll
    for (int i = 0; i < 4; i++) {
        float4 v = h4[t + i * 256];
        any |= (v.x != 0.f) | (v.y != 0.f) | (v.z != 0.f) | (v.w != 0.f);
    }
    int r = __syncthreads_or(any);
    if (t == 0) g_hflag = (r != 0);
}

// 8-loads-in-flight sequential dot of one 4-row slab chunk.
// base: float4 pointer to slab; sv: float4 vector (smem xi); returns row dots.
#define ROW_GROUP(PTR, VEC_LD, ACC)                                   \
    {                                                                 \
        float4 v0 = (PTR)[k0], v1 = (PTR)[k1], v2 = (PTR)[k2],        \
               v3 = (PTR)[k3], v4 = (PTR)[k4], v5 = (PTR)[k5],        \
               v6 = (PTR)[k6], v7 = (PTR)[k7];                        \
        ACC += dot4(v0, VEC_LD(c0i)); ACC += dot4(v1, VEC_LD(c1i));   \
        ACC += dot4(v2, VEC_LD(c2i)); ACC += dot4(v3, VEC_LD(c3i));   \
        ACC += dot4(v4, VEC_LD(c4i)); ACC += dot4(v5, VEC_LD(c5i));   \
        ACC += dot4(v6, VEC_LD(c6i)); ACC += dot4(v7, VEC_LD(c7i));   \
    }

// ---------------------------------------------------------------------------
// Fused persistent kernel. 512 blocks x 256 threads, all co-resident
// (__launch_bounds__(256,4): 4*148 = 592 >= 512) -> spins can't deadlock.
//   A: warp gw -> xi[gw]                                   (W_in,  16 MB)
//   B: warp gw -> 4 CONSECUTIVE stacked gate rows [4gw,4gw+4)
//      as ONE sequential 64 KB stream                      (W_ih, 268 MB)
//   P: lane0 of warp gw -> LSTM pointwise for j = gw
//   C: block -> 2 output rows                              (W_out, 16 MB)
// ---------------------------------------------------------------------------
__global__ __launch_bounds__(256, 4) void k_fused(
    const float* __restrict__ x,    const float* __restrict__ W_in,
    const float* __restrict__ b_in, const float* __restrict__ W_ih,
    const float* __restrict__ W_hh, const float* __restrict__ b_ih,
    const float* __restrict__ b_hh, const float* __restrict__ h0,
    const float* __restrict__ c0,   const float* __restrict__ W_out,
    const float* __restrict__ b_out, float* __restrict__ out)
{
    const int t = threadIdx.x;
    const int w = t >> 5, lane = t & 31;
    const int gw = blockIdx.x * 8 + w;  // 0..4095

    __shared__ __align__(16) float sbuf[H];  // 16 KB (x, then xi)
    __shared__ float spart[2][4];
    float4* s4 = (float4*)sbuf;

    // ---- Phase A: xi[gw] = W_in[gw,:] . x + b_in[gw]
    s4[t] = ((const float4*)x)[t];
    __syncthreads();
    {
        const float4* __restrict__ wr = (const float4*)(W_in + (size_t)gw * E);
        float acc = 0.f;
        #pragma unroll
        for (int i = 0; i < 8; i++)
            acc += dot4(wr[lane + 32 * i], s4[lane + 32 * i]);
        #pragma unroll
        for (int o = 16; o; o >>= 1) acc += __shfl_down_sync(0xFFFFFFFFu, acc, o);
        if (lane == 0) {
            g_xi[gw] = acc + b_in[gw];
            __threadfence();
        }
    }
    __syncthreads();                       // all warps' xi writes fenced
    if (t == 0) {
        atomicAdd(&g_xi_done, 1);
        volatile int* p = &g_xi_done;
        while (*p < 512) { }
    }
    __syncthreads();
    {   // stage full xi to smem (L2-coherent reads)
        const float4* gxi4 = (const float4*)g_xi;
        #pragma unroll
        for (int i = 0; i < 4; i++)
            s4[t + i * 256] = __ldcg(gxi4 + t + i * 256);
    }
    __syncthreads();

    // ---- Phase B: one contiguous 64 KB slab = stacked rows [4gw, 4gw+4)
    const int hflag = g_hflag;  // uniform
    float racc[4];
    {
        const float4* __restrict__ slab =
            (const float4*)(W_ih + (size_t)gw * 4 * H);
        #pragma unroll
        for (int r = 0; r < 4; r++) {
            float a = 0.f;
            #pragma unroll
            for (int gp = 0; gp < 4; gp++) {
                const int base = gp * 8;
                const int c0i = lane + 32 * (base + 0), k0 = r * 1024 + c0i;
                const int c1i = lane + 32 * (base + 1), k1 = r * 1024 + c1i;
                const int c2i = lane + 32 * (base + 2), k2 = r * 1024 + c2i;
                const int c3i = lane + 32 * (base + 3), k3 = r * 1024 + c3i;
                const int c4i = lane + 32 * (base + 4), k4 = r * 1024 + c4i;
                const int c5i = lane + 32 * (base + 5), k5 = r * 1024 + c5i;
                const int c6i = lane + 32 * (base + 6), k6 = r * 1024 + c6i;
                const int c7i = lane + 32 * (base + 7), k7 = r * 1024 + c7i;
                #define SLD(ci) (s4[ci])
                ROW_GROUP(slab, SLD, a)
                #undef SLD
            }
            racc[r] = a;
        }
    }

    if (hflag) {  // uniform; skipped when h0 == 0
        const float4* __restrict__ slab =
            (const float4*)(W_hh + (size_t)gw * 4 * H);
        const float4* __restrict__ h4 = (const float4*)h0;
        #pragma unroll
        for (int r = 0; r < 4; r++) {
            float a = 0.f;
            #pragma unroll
            for (int gp = 0; gp < 4; gp++) {
                const int base = gp * 8;
                const int c0i = lane + 32 * (base + 0), k0 = r * 1024 + c0i;
                const int c1i = lane + 32 * (base + 1), k1 = r * 1024 + c1i;
                const int c2i = lane + 32 * (base + 2), k2 = r * 1024 + c2i;
                const int c3i = lane + 32 * (base + 3), k3 = r * 1024 + c3i;
                const int c4i = lane + 32 * (base + 4), k4 = r * 1024 + c4i;
                const int c5i = lane + 32 * (base + 5), k5 = r * 1024 + c5i;
                const int c6i = lane + 32 * (base + 6), k6 = r * 1024 + c6i;
                const int c7i = lane + 32 * (base + 7), k7 = r * 1024 + c7i;
                #define HLD(ci) (__ldg(h4 + (ci)))
                ROW_GROUP(slab, HLD, a)
                #undef HLD
            }
            racc[r] += a;
        }
    }

    #pragma unroll
    for (int o = 16; o; o >>= 1) {
        racc[0] += __shfl_down_sync(0xFFFFFFFFu, racc[0], o);
        racc[1] += __shfl_down_sync(0xFFFFFFFFu, racc[1], o);
        racc[2] += __shfl_down_sync(0xFFFFFFFFu, racc[2], o);
        racc[3] += __shfl_down_sync(0xFFFFFFFFu, racc[3], o);
    }
    if (lane == 0) {
        float4 o4 = make_float4(racc[0], racc[1], racc[2], racc[3]);
        ((float4*)g_gates)[gw] = o4;   // rows 4gw..4gw+3
        __threadfence();
    }
    __syncthreads();
    if (t == 0) {
        atomicAdd(&g_gates_done, 1);
        volatile int* p = &g_gates_done;
        while (*p < 512) { }
    }
    __syncthreads();

    // ---- Pointwise: lane0 of warp w handles j = gw
    if (lane == 0) {
        const int j = gw;
        float vi = __ldcg(g_gates + j)         + b_ih[j]         + b_hh[j];
        float vf = __ldcg(g_gates + H + j)     + b_ih[H + j]     + b_hh[H + j];
        float vg = __ldcg(g_gates + 2 * H + j) + b_ih[2 * H + j] + b_hh[2 * H + j];
        float vo = __ldcg(g_gates + 3 * H + j) + b_ih[3 * H + j] + b_hh[3 * H + j];
        float c1 = sigmoidf(vf) * c0[j] + sigmoidf(vi) * tanhf(vg);
        float h1v = sigmoidf(vo) * tanhf(c1);
        out[E + j]     = h1v;   // h1 region
        out[E + H + j] = c1;    // c1 region
        g_h1[j] = h1v;
        __threadfence();
    }
    __syncthreads();
    if (t == 0) {
        atomicAdd(&g_h1_done, 1);
        volatile int* p = &g_h1_done;
        while (*p < 512) { }
    }
    __syncthreads();

    // ---- Phase C: 2 output rows per block, 4 warps per row (4 KB quarters)
    {
        const int rlocal = w >> 2;   // 0 or 1
        const int q = w & 3;         // quarter of the row
        const int row = blockIdx.x * 2 + rlocal;
        const float4* __restrict__ wr = (const float4*)(W_out + (size_t)row * H);
        const float4* __restrict__ h4 = (const float4*)g_h1;
        float acc = 0.f;
        #pragma unroll
        for (int i = 0; i < 8; i++) {
            const int k = q * 256 + lane + 32 * i;
            acc += dot4(wr[k], __ldcg(h4 + k));
        }
        #pragma unroll
        for (int o = 16; o; o >>= 1) acc += __shfl_down_sync(0xFFFFFFFFu, acc, o);
        if (lane == 0) spart[rlocal][q] = acc;
        __syncthreads();
        if (t < 2) {
            float s = spart[t][0] + spart[t][1] + spart[t][2] + spart[t][3];
            const int r = blockIdx.x * 2 + t;
            out[r] = s + b_out[r];
        }
    }
}

// ---------------------------------------------------------------------------
// Inputs (metadata order): 0:x 1:h0 2:c0 3:W_in 4:b_in 5:W_ih 6:W_hh
//                          7:b_ih 8:b_hh 9:W_out 10:b_out
// Output layout: [out (1024), h1 (4096), c1 (4096)]
// ---------------------------------------------------------------------------
extern "C" void kernel_launch(void* const* d_in, const int* in_sizes, int n_in,
                              void* d_out, int out_size) {
    const float* x     = (const float*)d_in[0];
    const float* h0    = (const float*)d_in[1];
    const float* c0    = (const float*)d_in[2];
    const float* W_in  = (const float*)d_in[3];
    const float* b_in  = (const float*)d_in[4];
    const float* W_ih  = (const float*)d_in[5];
    const float* W_hh  = (const float*)d_in[6];
    const float* b_ih  = (const float*)d_in[7];
    const float* b_hh  = (const float*)d_in[8];
    const float* W_out = (const float*)d_in[9];
    const float* b_out = (const float*)d_in[10];
    float* out = (float*)d_out;

    k_init<<<1, 256>>>(h0);
    k_fused<<<512, 256>>>(x, W_in, b_in, W_ih, W_hh, b_ih, b_hh,
                          h0, c0, W_out, b_out, out);
}

// round 14
// speedup vs baseline: 1.0031x; 1.0031x over previous
#include <cuda_runtime.h>
#include <math.h>

#define E 1024
#define H 4096

// Scratch (allocation-free per harness rules)
__device__ __align__(16) float g_xi[H];
__device__ __align__(16) float g_gates[4 * H];  // raw dot per stacked row
__device__ __align__(16) float g_h1[H];
__device__ int g_xi_done;     // blocks finished phase A   (target 512)
__device__ int g_gates_done;  // blocks finished phase B   (target 512)
__device__ int g_h1_done;     // blocks finished pointwise (target 512)
__device__ int g_hflag;

__device__ __forceinline__ float sigmoidf(float x) {
    return 1.0f / (1.0f + expf(-x));
}
__device__ __forceinline__ float dot4(float4 a, float4 b) {
    return a.x * b.x + a.y * b.y + a.z * b.z + a.w * b.w;
}

// ---------------------------------------------------------------------------
// K0: reset counters (graph replays reuse globals) + hflag = any(h0 != 0)
// ---------------------------------------------------------------------------
__global__ void k_init(const float* __restrict__ h0) {
    const int t = threadIdx.x;  // 256
    if (t == 0)  g_xi_done = 0;
    if (t == 32) g_gates_done = 0;
    if (t == 64) g_h1_done = 0;
    const float4* h4 = (const float4*)h0;
    int any = 0;
    #pragma unroll
    for (int i = 0; i < 4; i++) {
        float4 v = h4[t + i * 256];
        any |= (v.x != 0.f) | (v.y != 0.f) | (v.z != 0.f) | (v.w != 0.f);
    }
    int r = __syncthreads_or(any);
    if (t == 0) g_hflag = (r != 0);
}

// 8-loads-in-flight sequential dot of one 4-row slab chunk.
// base: float4 pointer to slab; sv: float4 vector (smem xi); returns row dots.
#define ROW_GROUP(PTR, VEC_LD, ACC)                                   \
    {                                                                 \
        float4 v0 = (PTR)[k0], v1 = (PTR)[k1], v2 = (PTR)[k2],        \
               v3 = (PTR)[k3], v4 = (PTR)[k4], v5 = (PTR)[k5],        \
               v6 = (PTR)[k6], v7 = (PTR)[k7];                        \
        ACC += dot4(v0, VEC_LD(c0i)); ACC += dot4(v1, VEC_LD(c1i));   \
        ACC += dot4(v2, VEC_LD(c2i)); ACC += dot4(v3, VEC_LD(c3i));   \
        ACC += dot4(v4, VEC_LD(c4i)); ACC += dot4(v5, VEC_LD(c5i));   \
        ACC += dot4(v6, VEC_LD(c6i)); ACC += dot4(v7, VEC_LD(c7i));   \
    }

// ---------------------------------------------------------------------------
// Fused persistent kernel. 512 blocks x 256 threads, all co-resident
// (__launch_bounds__(256,4): 4*148 = 592 >= 512) -> spins can't deadlock.
//   A: warp gw -> xi[gw]                                   (W_in,  16 MB)
//   B: warp gw -> 4 CONSECUTIVE stacked gate rows [4gw,4gw+4)
//      as ONE sequential 64 KB stream                      (W_ih, 268 MB)
//   P: lane0 of warp gw -> LSTM pointwise for j = gw
//   C: block -> 2 output rows                              (W_out, 16 MB)
// ---------------------------------------------------------------------------
__global__ __launch_bounds__(256, 4) void k_fused(
    const float* __restrict__ x,    const float* __restrict__ W_in,
    const float* __restrict__ b_in, const float* __restrict__ W_ih,
    const float* __restrict__ W_hh, const float* __restrict__ b_ih,
    const float* __restrict__ b_hh, const float* __restrict__ h0,
    const float* __restrict__ c0,   const float* __restrict__ W_out,
    const float* __restrict__ b_out, float* __restrict__ out)
{
    const int t = threadIdx.x;
    const int w = t >> 5, lane = t & 31;
    const int gw = blockIdx.x * 8 + w;  // 0..4095

    __shared__ __align__(16) float sbuf[H];  // 16 KB (x, then xi)
    __shared__ float spart[2][4];
    float4* s4 = (float4*)sbuf;

    // ---- Phase A: xi[gw] = W_in[gw,:] . x + b_in[gw]
    s4[t] = ((const float4*)x)[t];
    __syncthreads();
    {
        const float4* __restrict__ wr = (const float4*)(W_in + (size_t)gw * E);
        float acc = 0.f;
        #pragma unroll
        for (int i = 0; i < 8; i++)
            acc += dot4(wr[lane + 32 * i], s4[lane + 32 * i]);
        #pragma unroll
        for (int o = 16; o; o >>= 1) acc += __shfl_down_sync(0xFFFFFFFFu, acc, o);
        if (lane == 0) {
            g_xi[gw] = acc + b_in[gw];
            __threadfence();
        }
    }
    __syncthreads();                       // all warps' xi writes fenced
    if (t == 0) {
        atomicAdd(&g_xi_done, 1);
        volatile int* p = &g_xi_done;
        while (*p < 512) { }
    }
    __syncthreads();
    {   // stage full xi to smem (L2-coherent reads)
        const float4* gxi4 = (const float4*)g_xi;
        #pragma unroll
        for (int i = 0; i < 4; i++)
            s4[t + i * 256] = __ldcg(gxi4 + t + i * 256);
    }
    __syncthreads();

    // ---- Phase B: one contiguous 64 KB slab = stacked rows [4gw, 4gw+4)
    const int hflag = g_hflag;  // uniform
    float racc[4];
    {
        const float4* __restrict__ slab =
            (const float4*)(W_ih + (size_t)gw * 4 * H);
        #pragma unroll
        for (int r = 0; r < 4; r++) {
            float a = 0.f;
            #pragma unroll
            for (int gp = 0; gp < 4; gp++) {
                const int base = gp * 8;
                const int c0i = lane + 32 * (base + 0), k0 = r * 1024 + c0i;
                const int c1i = lane + 32 * (base + 1), k1 = r * 1024 + c1i;
                const int c2i = lane + 32 * (base + 2), k2 = r * 1024 + c2i;
                const int c3i = lane + 32 * (base + 3), k3 = r * 1024 + c3i;
                const int c4i = lane + 32 * (base + 4), k4 = r * 1024 + c4i;
                const int c5i = lane + 32 * (base + 5), k5 = r * 1024 + c5i;
                const int c6i = lane + 32 * (base + 6), k6 = r * 1024 + c6i;
                const int c7i = lane + 32 * (base + 7), k7 = r * 1024 + c7i;
                #define SLD(ci) (s4[ci])
                ROW_GROUP(slab, SLD, a)
                #undef SLD
            }
            racc[r] = a;
        }
    }

    if (hflag) {  // uniform; skipped when h0 == 0
        const float4* __restrict__ slab =
            (const float4*)(W_hh + (size_t)gw * 4 * H);
        const float4* __restrict__ h4 = (const float4*)h0;
        #pragma unroll
        for (int r = 0; r < 4; r++) {
            float a = 0.f;
            #pragma unroll
            for (int gp = 0; gp < 4; gp++) {
                const int base = gp * 8;
                const int c0i = lane + 32 * (base + 0), k0 = r * 1024 + c0i;
                const int c1i = lane + 32 * (base + 1), k1 = r * 1024 + c1i;
                const int c2i = lane + 32 * (base + 2), k2 = r * 1024 + c2i;
                const int c3i = lane + 32 * (base + 3), k3 = r * 1024 + c3i;
                const int c4i = lane + 32 * (base + 4), k4 = r * 1024 + c4i;
                const int c5i = lane + 32 * (base + 5), k5 = r * 1024 + c5i;
                const int c6i = lane + 32 * (base + 6), k6 = r * 1024 + c6i;
                const int c7i = lane + 32 * (base + 7), k7 = r * 1024 + c7i;
                #define HLD(ci) (__ldg(h4 + (ci)))
                ROW_GROUP(slab, HLD, a)
                #undef HLD
            }
            racc[r] += a;
        }
    }

    #pragma unroll
    for (int o = 16; o; o >>= 1) {
        racc[0] += __shfl_down_sync(0xFFFFFFFFu, racc[0], o);
        racc[1] += __shfl_down_sync(0xFFFFFFFFu, racc[1], o);
        racc[2] += __shfl_down_sync(0xFFFFFFFFu, racc[2], o);
        racc[3] += __shfl_down_sync(0xFFFFFFFFu, racc[3], o);
    }
    if (lane == 0) {
        float4 o4 = make_float4(racc[0], racc[1], racc[2], racc[3]);
        ((float4*)g_gates)[gw] = o4;   // rows 4gw..4gw+3
        __threadfence();
    }
    __syncthreads();
    if (t == 0) {
        atomicAdd(&g_gates_done, 1);
        volatile int* p = &g_gates_done;
        while (*p < 512) { }
    }
    __syncthreads();

    // ---- Pointwise: lane0 of warp w handles j = gw
    if (lane == 0) {
        const int j = gw;
        float vi = __ldcg(g_gates + j)         + b_ih[j]         + b_hh[j];
        float vf = __ldcg(g_gates + H + j)     + b_ih[H + j]     + b_hh[H + j];
        float vg = __ldcg(g_gates + 2 * H + j) + b_ih[2 * H + j] + b_hh[2 * H + j];
        float vo = __ldcg(g_gates + 3 * H + j) + b_ih[3 * H + j] + b_hh[3 * H + j];
        float c1 = sigmoidf(vf) * c0[j] + sigmoidf(vi) * tanhf(vg);
        float h1v = sigmoidf(vo) * tanhf(c1);
        out[E + j]     = h1v;   // h1 region
        out[E + H + j] = c1;    // c1 region
        g_h1[j] = h1v;
        __threadfence();
    }
    __syncthreads();
    if (t == 0) {
        atomicAdd(&g_h1_done, 1);
        volatile int* p = &g_h1_done;
        while (*p < 512) { }
    }
    __syncthreads();

    // ---- Phase C: 2 output rows per block, 4 warps per row (4 KB quarters)
    {
        const int rlocal = w >> 2;   // 0 or 1
        const int q = w & 3;         // quarter of the row
        const int row = blockIdx.x * 2 + rlocal;
        const float4* __restrict__ wr = (const float4*)(W_out + (size_t)row * H);
        const float4* __restrict__ h4 = (const float4*)g_h1;
        float acc = 0.f;
        #pragma unroll
        for (int i = 0; i < 8; i++) {
            const int k = q * 256 + lane + 32 * i;
            acc += dot4(wr[k], __ldcg(h4 + k));
        }
        #pragma unroll
        for (int o = 16; o; o >>= 1) acc += __shfl_down_sync(0xFFFFFFFFu, acc, o);
        if (lane == 0) spart[rlocal][q] = acc;
        __syncthreads();
        if (t < 2) {
            float s = spart[t][0] + spart[t][1] + spart[t][2] + spart[t][3];
            const int r = blockIdx.x * 2 + t;
            out[r] = s + b_out[r];
        }
    }
}

// ---------------------------------------------------------------------------
// Inputs (metadata order): 0:x 1:h0 2:c0 3:W_in 4:b_in 5:W_ih 6:W_hh
//                          7:b_ih 8:b_hh 9:W_out 10:b_out
// Output layout: [out (1024), h1 (4096), c1 (4096)]
// ---------------------------------------------------------------------------
extern "C" void kernel_launch(void* const* d_in, const int* in_sizes, int n_in,
                              void* d_out, int out_size) {
    const float* x     = (const float*)d_in[0];
    const float* h0    = (const float*)d_in[1];
    const float* c0    = (const float*)d_in[2];
    const float* W_in  = (const float*)d_in[3];
    const float* b_in  = (const float*)d_in[4];
    const float* W_ih  = (const float*)d_in[5];
    const float* W_hh  = (const float*)d_in[6];
    const float* b_ih  = (const float*)d_in[7];
    const float* b_hh  = (const float*)d_in[8];
    const float* W_out = (const float*)d_in[9];
    const float* b_out = (const float*)d_in[10];
    float* out = (float*)d_out;

    k_init<<<1, 256>>>(h0);
    k_fused<<<512, 256>>>(x, W_in, b_in, W_ih, W_hh, b_ih, b_hh,
                          h0, c0, W_out, b_out, out);
}

// round 15
// speedup vs baseline: 1.0497x; 1.0465x over previous
#include <cuda_runtime.h>
#include <math.h>

#define E 1024
#define H 4096

// Scratch (allocation-free per harness rules). Static zero-init is the
// first-call state; the kernel restores counters to 0 at the end of every
// call (last-block reset), so every graph replay starts clean.
__device__ __align__(16) float g_xi[H];
__device__ __align__(16) float g_gates[4 * H];
__device__ __align__(16) float g_h1[H];
__device__ int g_a = 0;      // blocks past phase A   (target 512)
__device__ int g_b = 0;      // blocks past phase B   (target 512)
__device__ int g_c = 0;      // blocks past pointwise (target 512)
__device__ int g_exit = 0;   // exit ticket; last block resets everything
__device__ int g_hflag;

__device__ __forceinline__ float sigmoidf(float x) {
    return 1.0f / (1.0f + expf(-x));
}
__device__ __forceinline__ float dot4(float4 a, float4 b) {
    return a.x * b.x + a.y * b.y + a.z * b.z + a.w * b.w;
}

// ---------------------------------------------------------------------------
// Single fused persistent kernel. 512 blocks x 256 threads, all co-resident
// (__launch_bounds__(256,4): 4*148 = 592 >= 512) -> spins cannot deadlock.
//   A: warp gw -> xi[gw]; block 0 also computes hflag     (W_in,  16 MB)
//   B: warp gw -> stacked gate rows [4gw,4gw+4) as one 64 KB slab,
//      column-grouped so each xi float4 is loaded once and reused 4x
//                                                          (W_ih, 268 MB)
//   P: lane0 of warp gw -> LSTM pointwise for j = gw
//   C: block -> 2 output rows                              (W_out, 16 MB)
//   End: last block resets counters for the next graph replay.
// ---------------------------------------------------------------------------
__global__ __launch_bounds__(256, 4) void k_fused(
    const float* __restrict__ x,    const float* __restrict__ W_in,
    const float* __restrict__ b_in, const float* __restrict__ W_ih,
    const float* __restrict__ W_hh, const float* __restrict__ b_ih,
    const float* __restrict__ b_hh, const float* __restrict__ h0,
    const float* __restrict__ c0,   const float* __restrict__ W_out,
    const float* __restrict__ b_out, float* __restrict__ out)
{
    const int t = threadIdx.x;
    const int w = t >> 5, lane = t & 31;
    const int gw = blockIdx.x * 8 + w;  // 0..4095

    __shared__ __align__(16) float sbuf[H];  // 16 KB (x, then xi)
    __shared__ float spart[2][4];
    float4* s4 = (float4*)sbuf;

    const float4* __restrict__ slab = (const float4*)(W_ih + (size_t)gw * 4 * H);

    // Prefetch first 8 KB of this warp's W_ih slab into L2 (overlaps phase A).
    {
        const char* pf = (const char*)slab;
        #pragma unroll
        for (int i = 0; i < 2; i++)
            asm volatile("prefetch.global.L2 [%0];"
                         :: "l"(pf + (size_t)(lane + 32 * i) * 128));
    }

    // ---- Phase A: xi[gw] = W_in[gw,:] . x + b_in[gw]
    s4[t] = ((const float4*)x)[t];
    __syncthreads();
    {
        const float4* __restrict__ wr = (const float4*)(W_in + (size_t)gw * E);
        float acc = 0.f;
        #pragma unroll
        for (int i = 0; i < 8; i++)
            acc += dot4(wr[lane + 32 * i], s4[lane + 32 * i]);
        #pragma unroll
        for (int o = 16; o; o >>= 1) acc += __shfl_down_sync(0xFFFFFFFFu, acc, o);
        if (lane == 0) {
            g_xi[gw] = acc + b_in[gw];
            __threadfence();
        }
    }
    // Block 0 additionally computes hflag = any(h0 != 0).
    if (blockIdx.x == 0) {
        const float4* h4 = (const float4*)h0;
        int any = 0;
        #pragma unroll
        for (int i = 0; i < 4; i++) {
            float4 v = h4[t + i * 256];
            any |= (v.x != 0.f) | (v.y != 0.f) | (v.z != 0.f) | (v.w != 0.f);
        }
        int r = __syncthreads_or(any);
        if (t == 0) { g_hflag = (r != 0); __threadfence(); }
    }
    __syncthreads();
    if (t == 0) {
        atomicAdd(&g_a, 1);
        volatile int* p = &g_a;
        while (*p < 512) { }
    }
    __syncthreads();
    {   // stage full xi to smem (L2-coherent reads)
        const float4* gxi4 = (const float4*)g_xi;
        #pragma unroll
        for (int i = 0; i < 4; i++)
            s4[t + i * 256] = __ldcg(gxi4 + t + i * 256);
    }
    __syncthreads();

    // ---- Phase B: slab rows [4gw,4gw+4), column-grouped (xi reused 4x)
    const int hflag = __ldcg(&g_hflag);  // uniform
    float a0 = 0.f, a1 = 0.f, a2 = 0.f, a3 = 0.f;

    for (int cg = 0; cg < 32; cg += 2) {
        const int c0i = cg * 32 + lane;
        const int c1i = c0i + 32;
        float4 x0 = s4[c0i], x1 = s4[c1i];
        float4 w00 = slab[c0i],          w01 = slab[c1i];
        float4 w10 = slab[1024 + c0i],   w11 = slab[1024 + c1i];
        float4 w20 = slab[2048 + c0i],   w21 = slab[2048 + c1i];
        float4 w30 = slab[3072 + c0i],   w31 = slab[3072 + c1i];
        a0 += dot4(w00, x0) + dot4(w01, x1);
        a1 += dot4(w10, x0) + dot4(w11, x1);
        a2 += dot4(w20, x0) + dot4(w21, x1);
        a3 += dot4(w30, x0) + dot4(w31, x1);
    }

    if (hflag) {  // uniform; skipped when h0 == 0 (h0 hits L2, reused)
        const float4* __restrict__ hslab =
            (const float4*)(W_hh + (size_t)gw * 4 * H);
        const float4* __restrict__ h4 = (const float4*)h0;
        for (int cg = 0; cg < 32; cg += 2) {
            const int c0i = cg * 32 + lane;
            const int c1i = c0i + 32;
            float4 x0 = __ldg(h4 + c0i), x1 = __ldg(h4 + c1i);
            float4 w00 = hslab[c0i],          w01 = hslab[c1i];
            float4 w10 = hslab[1024 + c0i],   w11 = hslab[1024 + c1i];
            float4 w20 = hslab[2048 + c0i],   w21 = hslab[2048 + c1i];
            float4 w30 = hslab[3072 + c0i],   w31 = hslab[3072 + c1i];
            a0 += dot4(w00, x0) + dot4(w01, x1);
            a1 += dot4(w10, x0) + dot4(w11, x1);
            a2 += dot4(w20, x0) + dot4(w21, x1);
            a3 += dot4(w30, x0) + dot4(w31, x1);
        }
    }

    #pragma unroll
    for (int o = 16; o; o >>= 1) {
        a0 += __shfl_down_sync(0xFFFFFFFFu, a0, o);
        a1 += __shfl_down_sync(0xFFFFFFFFu, a1, o);
        a2 += __shfl_down_sync(0xFFFFFFFFu, a2, o);
        a3 += __shfl_down_sync(0xFFFFFFFFu, a3, o);
    }
    if (lane == 0) {
        ((float4*)g_gates)[gw] = make_float4(a0, a1, a2, a3);  // rows 4gw..+3
        __threadfence();
    }
    __syncthreads();
    if (t == 0) {
        atomicAdd(&g_b, 1);
        volatile int* p = &g_b;
        while (*p < 512) { }
    }
    __syncthreads();

    // ---- Pointwise: lane0 of warp w handles j = gw
    if (lane == 0) {
        const int j = gw;
        float vi = __ldcg(g_gates + j)         + b_ih[j]         + b_hh[j];
        float vf = __ldcg(g_gates + H + j)     + b_ih[H + j]     + b_hh[H + j];
        float vg = __ldcg(g_gates + 2 * H + j) + b_ih[2 * H + j] + b_hh[2 * H + j];
        float vo = __ldcg(g_gates + 3 * H + j) + b_ih[3 * H + j] + b_hh[3 * H + j];
        float c1 = sigmoidf(vf) * c0[j] + sigmoidf(vi) * tanhf(vg);
        float h1v = sigmoidf(vo) * tanhf(c1);
        out[E + j]     = h1v;   // h1 region
        out[E + H + j] = c1;    // c1 region
        g_h1[j] = h1v;
        __threadfence();
    }
    __syncthreads();
    if (t == 0) {
        atomicAdd(&g_c, 1);
        volatile int* p = &g_c;
        while (*p < 512) { }
        // Exit ticket: the LAST block to arrive knows every block has passed
        // every spin above, so it can safely reset counters for next replay.
        int old = atomicAdd(&g_exit, 1);
        if (old == 511) {
            g_a = 0; g_b = 0; g_c = 0; g_exit = 0;
            __threadfence();
        }
    }
    __syncthreads();

    // ---- Phase C: 2 output rows per block, 4 warps per row (4 KB quarters)
    {
        const int rlocal = w >> 2;   // 0 or 1
        const int q = w & 3;         // quarter of the row
        const int row = blockIdx.x * 2 + rlocal;
        const float4* __restrict__ wr = (const float4*)(W_out + (size_t)row * H);
        const float4* __restrict__ h4 = (const float4*)g_h1;
        float acc = 0.f;
        #pragma unroll
        for (int i = 0; i < 8; i++) {
            const int k = q * 256 + lane + 32 * i;
            acc += dot4(wr[k], __ldcg(h4 + k));
        }
        #pragma unroll
        for (int o = 16; o; o >>= 1) acc += __shfl_down_sync(0xFFFFFFFFu, acc, o);
        if (lane == 0) spart[rlocal][q] = acc;
        __syncthreads();
        if (t < 2) {
            float s = spart[t][0] + spart[t][1] + spart[t][2] + spart[t][3];
            const int r = blockIdx.x * 2 + t;
            out[r] = s + b_out[r];
        }
    }
}

// ---------------------------------------------------------------------------
// Inputs (metadata order): 0:x 1:h0 2:c0 3:W_in 4:b_in 5:W_ih 6:W_hh
//                          7:b_ih 8:b_hh 9:W_out 10:b_out
// Output layout: [out (1024), h1 (4096), c1 (4096)]
// ---------------------------------------------------------------------------
extern "C" void kernel_launch(void* const* d_in, const int* in_sizes, int n_in,
                              void* d_out, int out_size) {
    const float* x     = (const float*)d_in[0];
    const float* h0    = (const float*)d_in[1];
    const float* c0    = (const float*)d_in[2];
    const float* W_in  = (const float*)d_in[3];
    const float* b_in  = (const float*)d_in[4];
    const float* W_ih  = (const float*)d_in[5];
    const float* W_hh  = (const float*)d_in[6];
    const float* b_ih  = (const float*)d_in[7];
    const float* b_hh  = (const float*)d_in[8];
    const float* W_out = (const float*)d_in[9];
    const float* b_out = (const float*)d_in[10];
    float* out = (float*)d_out;

    k_fused<<<512, 256>>>(x, W_in, b_in, W_ih, W_hh, b_ih, b_hh,
                          h0, c0, W_out, b_out, out);
}